// round 6
// baseline (speedup 1.0000x reference)
#include <cuda_runtime.h>

// ---------------------------------------------------------------------------
// InferCellV1 on GB300 — fp32: prefix trick (8x FLOP cut) + fma.rn.f32x2
// + double-buffered smem staging (overlap LDG with FMA) + division-free
// float4 staging + shfl-butterfly BN stats.
// ---------------------------------------------------------------------------

typedef unsigned long long u64;
#define EPSV 1e-5f

__device__ float  g_C1[(size_t)64 * 64 * 1024];          // conv1 out (16.7 MB)
__device__ float  g_P [(size_t)8 * 64 * 64 * 1024];      // prefix outs (134 MB)
__device__ float  g_N1[(size_t)64 * 64 * 1024];
__device__ float  g_N2[(size_t)64 * 64 * 1024];
__device__ float2 g_part1[64 * 64];                      // [c][b]
__device__ float2 g_part2[8 * 64 * 64];                  // [k][c][b]
__device__ float  g_scale1[64], g_shift1[64];
__device__ float  g_scaleP[8 * 64];
__device__ float  g_biasP[64];
__device__ float  g_m1v[64], g_cmv[64];

__device__ __forceinline__ u64 fma2(u64 a, u64 b, u64 c) {
    u64 d; asm("fma.rn.f32x2 %0, %1, %2, %3;" : "=l"(d) : "l"(a), "l"(b), "l"(c)); return d;
}
__device__ __forceinline__ u64 pack2(float x, float y) {
    u64 d; asm("mov.b64 %0, {%1, %2};" : "=l"(d) : "f"(x), "f"(y)); return d;
}
__device__ __forceinline__ float2 unpack2(u64 v) {
    float2 r; asm("mov.b64 {%0, %1}, %2;" : "=f"(r.x), "=f"(r.y) : "l"(v)); return r;
}

__global__ void prep_kernel(const float* __restrict__ a1, const float* __restrict__ a2) {
    int c = threadIdx.x;
    int g = c >> 3;
    float s1 = 0.f, s2 = 0.f;
    for (int i = g; i < 8; ++i) { s1 += a1[i]; s2 += a2[i]; }
    g_m1v[c] = s1;
    g_cmv[c] = s1 * s2;
}

// Smem layout (floats), dynamic:
//   sIn  : 2 buffers x 8ci x 34rows x 40cols = 21760   (halo: row0/33, col3/36)
//   sW   : 2 buffers x 72 x 16oc             = 2304
//   sStat: 2 parity x 8 warps x 32           = 512
//   sSc  : 64 ; sSh : 64
#define CI_STRIDE   1360     // 34*40
#define BUF_STRIDE  10880    // 8*1360
#define SW_OFF      21760
#define SSTAT_OFF   24064
#define SSC_OFF     24576
#define SSH_OFF     24640
#define SMEM_FLOATS 24704
#define SMEM_BYTES  (SMEM_FLOATS * 4)

// 32-value cross-lane butterfly: lane L ends with sum over lanes of v[L].
__device__ __forceinline__ void warp_reduce32(float* v, int lane) {
#pragma unroll
    for (int d = 16; d >= 1; d >>= 1) {
#pragma unroll
        for (int i = 0; i < d; ++i) {
            float mine  = (lane & d) ? v[i + d] : v[i];
            float give  = (lane & d) ? v[i]     : v[i + d];
            float recv  = __shfl_xor_sync(0xffffffffu, give, d);
            v[i] = mine + recv;
        }
    }
}

// Stage one 8-ci group: interior rows as float4 (halo pre-zeroed) + weights.
template <int STAGE>
__device__ __forceinline__ void stage_group(
    float* __restrict__ dIn, float* __restrict__ dW,
    const float* __restrict__ src, const float* __restrict__ w,
    int b, int oc0, int cbase, int t,
    const float* __restrict__ sSc, const float* __restrict__ sSh)
{
    const int row   = t >> 3;   // 0..31
    const int chunk = t & 7;    // 0..7 (16B chunks)
    const float* sbase = src + (((size_t)b * 64 + cbase) << 10) + (row << 5) + (chunk << 2);
    float* dbase = dIn + (row + 1) * 40 + 4 + (chunk << 2);
#pragma unroll
    for (int ci = 0; ci < 8; ++ci) {
        float4 v = *reinterpret_cast<const float4*>(sbase + ((size_t)ci << 10));
        if (STAGE == 1) {
            v.x = fmaxf(v.x, 0.f); v.y = fmaxf(v.y, 0.f);
            v.z = fmaxf(v.z, 0.f); v.w = fmaxf(v.w, 0.f);
        } else {
            float sc = sSc[cbase + ci], sh = sSh[cbase + ci];
            v.x = fmaf(v.x, sc, sh); v.y = fmaf(v.y, sc, sh);
            v.z = fmaf(v.z, sc, sh); v.w = fmaf(v.w, sc, sh);
        }
        *reinterpret_cast<float4*>(dbase + ci * CI_STRIDE) = v;
    }
    // weights: [r=ci*9+tap][16 oc]
    for (int idx = t; idx < 1152; idx += 256) {
        int oc = idx & 15;
        int r  = idx >> 4;      // 0..71 = ci_local*9 + tap (contiguous in gmem)
        dW[idx] = w[((size_t)(oc0 + oc) * 64 + cbase) * 9 + r];
    }
}

// ---------------------------------------------------------------------------
// Conv: one image b x 16 oc x 32x32 per block; thread: 4 pixel-rows x 16 oc
// as 8 f32x2 accumulators. STAGE 1: relu->conv->g_C1 (+stats at end).
// STAGE 2: affine->conv, prefix P_k per group (+per-group stats).
// ---------------------------------------------------------------------------
template <int STAGE, int SRC>
__global__ __launch_bounds__(256, 2)
void conv_kernel(const float* __restrict__ in, const float* __restrict__ w) {
    extern __shared__ float smem[];
    float* sIn   = smem;
    float* sW    = smem + SW_OFF;
    float* sStat = smem + SSTAT_OFF;
    float* sSc   = smem + SSC_OFF;
    float* sSh   = smem + SSH_OFF;

    const int b    = blockIdx.x >> 2;
    const int oc0  = (blockIdx.x & 3) << 4;
    const int t    = threadIdx.x;
    const int tx   = t & 31;
    const int ty   = t >> 5;
    const int wid  = t >> 5;
    const int lane = t & 31;

    if (STAGE == 2 && t < 64) { sSc[t] = g_scale1[t]; sSh[t] = g_shift1[t]; }

    // one-time halo zero: both buffers, per ci: rows 0,33 (40 ea) + col 3,36 rows1..32
    for (int i = t; i < 2304; i += 256) {
        int bc = i / 144;             // buf*8+ci  (contiguous: bc*CI_STRIDE)
        int r  = i - bc * 144;
        float* base = sIn + bc * CI_STRIDE;
        if (r < 40)      base[r] = 0.f;
        else if (r < 80) base[33 * 40 + (r - 40)] = 0.f;
        else { int rr = r - 80; base[((rr >> 1) + 1) * 40 + ((rr & 1) ? 36 : 3)] = 0.f; }
    }

    u64 acc2[4][8];
#pragma unroll
    for (int p = 0; p < 4; ++p)
#pragma unroll
        for (int o2 = 0; o2 < 8; ++o2) acc2[p][o2] = 0ull;

    const float* src = (STAGE == 2) ? g_C1
                     : (SRC == 0)   ? in
                     : (SRC == 1)   ? g_N1
                                    : g_N2;

    __syncthreads();
    stage_group<STAGE>(sIn, sW, src, w, b, oc0, 0, t, sSc, sSh);
    __syncthreads();

    for (int cc = 0; cc < 8; ++cc) {
        const int cur = cc & 1;
        if (cc < 7)
            stage_group<STAGE>(sIn + (cur ^ 1) * BUF_STRIDE, sW + (cur ^ 1) * 1152,
                               src, w, b, oc0, (cc + 1) << 3, t, sSc, sSh);

        const float* buf = sIn + cur * BUF_STRIDE;
        const float* wb  = sW + cur * 1152;
#pragma unroll 1
        for (int ci = 0; ci < 8; ++ci) {
            const float* bci = buf + ci * CI_STRIDE;
            const float* wci = wb + (ci * 9 << 4);
#pragma unroll
            for (int ky = 0; ky < 3; ++ky) {
#pragma unroll
                for (int kx = 0; kx < 3; ++kx) {
                    const float* wrow = wci + ((ky * 3 + kx) << 4);
                    u64 wp[8];
#pragma unroll
                    for (int o2 = 0; o2 < 8; ++o2)
                        wp[o2] = *reinterpret_cast<const u64*>(wrow + (o2 << 1));
#pragma unroll
                    for (int p = 0; p < 4; ++p) {
                        float iv = bci[(ty + (p << 3) + ky) * 40 + tx + kx + 3];
                        u64 iv2 = pack2(iv, iv);
#pragma unroll
                        for (int o2 = 0; o2 < 8; ++o2)
                            acc2[p][o2] = fma2(iv2, wp[o2], acc2[p][o2]);
                    }
                }
            }
        }

        if (STAGE == 2) {
            // acc2 holds prefix P_cc: emit + stats
            float v[32];
#pragma unroll
            for (int o = 0; o < 32; ++o) v[o] = 0.f;
#pragma unroll
            for (int p = 0; p < 4; ++p) {
                int pix = ((ty + (p << 3)) << 5) + tx;
#pragma unroll
                for (int o2 = 0; o2 < 8; ++o2) {
                    float2 pv = unpack2(acc2[p][o2]);
                    size_t base = (((size_t)cc * 64 + b) * 64 + oc0 + (o2 << 1)) * 1024 + pix;
                    g_P[base]        = pv.x;
                    g_P[base + 1024] = pv.y;
                    v[2 * o2]          += pv.x;
                    v[16 + 2 * o2]     += pv.x * pv.x;
                    v[2 * o2 + 1]      += pv.y;
                    v[16 + 2 * o2 + 1] += pv.y * pv.y;
                }
            }
            warp_reduce32(v, lane);
            sStat[(cc & 1) * 256 + (wid << 5) + lane] = v[0];
        }
        __syncthreads();
        if (STAGE == 2 && t < 32) {
            float s = 0.f;
#pragma unroll
            for (int ww = 0; ww < 8; ++ww) s += sStat[(cc & 1) * 256 + (ww << 5) + lane];
            float qv = __shfl_down_sync(0xffffffffu, s, 16);
            if (lane < 16)
                g_part2[((size_t)cc * 64 + oc0 + lane) * 64 + b] = make_float2(s, qv);
        }
    }

    if (STAGE == 1) {
        float v[32];
#pragma unroll
        for (int o = 0; o < 32; ++o) v[o] = 0.f;
#pragma unroll
        for (int p = 0; p < 4; ++p) {
            int pix = ((ty + (p << 3)) << 5) + tx;
#pragma unroll
            for (int o2 = 0; o2 < 8; ++o2) {
                float2 pv = unpack2(acc2[p][o2]);
                size_t base = (((size_t)b * 64 + oc0 + (o2 << 1)) << 10) + pix;
                g_C1[base]        = pv.x;
                g_C1[base + 1024] = pv.y;
                v[2 * o2]          += pv.x;
                v[16 + 2 * o2]     += pv.x * pv.x;
                v[2 * o2 + 1]      += pv.y;
                v[16 + 2 * o2 + 1] += pv.y * pv.y;
            }
        }
        warp_reduce32(v, lane);
        sStat[(wid << 5) + lane] = v[0];
        __syncthreads();
        if (t < 32) {
            float s = 0.f;
#pragma unroll
            for (int ww = 0; ww < 8; ++ww) s += sStat[(ww << 5) + lane];
            float qv = __shfl_down_sync(0xffffffffu, s, 16);
            if (lane < 16)
                g_part1[(oc0 + lane) * 64 + b] = make_float2(s, qv);
        }
    }
}

// ---------------------------------------------------------------------------
__global__ void fin1_kernel() {  // <<<1,64>>>
    int c = threadIdx.x;
    float s = 0.f, q = 0.f;
    for (int b = 0; b < 64; ++b) { float2 v = g_part1[c * 64 + b]; s += v.x; q += v.y; }
    const float invN = 1.f / 65536.f;
    float mu   = s * invN;
    float var  = q * invN - mu * mu;
    float sc   = rsqrtf(var + EPSV) * g_m1v[c];
    g_scale1[c] = sc;
    g_shift1[c] = -mu * sc;
}

__global__ void fin2_kernel(const float* __restrict__ a2) {  // <<<1,64>>>
    int c = threadIdx.x;
    const float invN = 1.f / 65536.f;
    float bias = 0.f;
    for (int k = 0; k < 8; ++k) {
        float s = 0.f, q = 0.f;
        for (int b = 0; b < 64; ++b) { float2 v = g_part2[(k * 64 + c) * 64 + b]; s += v.x; q += v.y; }
        float mu  = s * invN;
        float var = q * invN - mu * mu;
        float wk  = a2[k] * rsqrtf(var + EPSV);
        g_scaleP[k * 64 + c] = wk;
        bias -= wk * mu;
    }
    g_biasP[c] = bias;
}

// ---------------------------------------------------------------------------
// Combine: out = sum_k scaleP[k,c]*P_k + biasP[c], float4-vectorized.
// MODE 0: -> g_N1 ; MODE 1: -> g_N2 + avgpool3(g_N1)*cm ;
// MODE 2: -> out + xin*cm ; MODE 3: out += acc
// ---------------------------------------------------------------------------
template <int MODE>
__global__ __launch_bounds__(256)
void combine_kernel(const float* __restrict__ xin, float* __restrict__ out) {
    int bc = blockIdx.x;
    int b = bc >> 6, c = bc & 63;
    int t = threadIdx.x;
    float sp[8];
#pragma unroll
    for (int k = 0; k < 8; ++k) sp[k] = g_scaleP[k * 64 + c];
    float bias = g_biasP[c];
    float cmv  = g_cmv[c];
    size_t base = ((size_t)b * 64 + c) << 10;
    int p0 = t << 2;

    float4 acc = make_float4(bias, bias, bias, bias);
#pragma unroll
    for (int k = 0; k < 8; ++k) {
        float4 v = *reinterpret_cast<const float4*>(
            &g_P[(((size_t)k * 64 + b) * 64 + c) * 1024 + p0]);
        acc.x = fmaf(sp[k], v.x, acc.x);
        acc.y = fmaf(sp[k], v.y, acc.y);
        acc.z = fmaf(sp[k], v.z, acc.z);
        acc.w = fmaf(sp[k], v.w, acc.w);
    }

    if (MODE == 0) {
        *reinterpret_cast<float4*>(&g_N1[base + p0]) = acc;
    }
    if (MODE == 1) {
        int y = p0 >> 5, x = p0 & 31;
        int y0 = max(y - 1, 0), y1 = min(y + 1, 31);
        float rs[6];
#pragma unroll
        for (int j = 0; j < 6; ++j) {
            int xx = x - 1 + j;
            float v = 0.f;
            if ((unsigned)xx < 32u)
                for (int yy = y0; yy <= y1; ++yy) v += g_N1[base + (yy << 5) + xx];
            rs[j] = v;
        }
        float nr = (float)(y1 - y0 + 1);
        float pool[4];
#pragma unroll
        for (int i = 0; i < 4; ++i) {
            int xi = x + i;
            int c0 = max(xi - 1, 0), c1 = min(xi + 1, 31);
            float cnt = nr * (float)(c1 - c0 + 1);
            pool[i] = (rs[i] + rs[i + 1] + rs[i + 2]) / cnt;
        }
        acc.x += pool[0] * cmv; acc.y += pool[1] * cmv;
        acc.z += pool[2] * cmv; acc.w += pool[3] * cmv;
        *reinterpret_cast<float4*>(&g_N2[base + p0]) = acc;
    }
    if (MODE == 2) {
        float4 xv = *reinterpret_cast<const float4*>(&xin[base + p0]);
        acc.x += xv.x * cmv; acc.y += xv.y * cmv;
        acc.z += xv.z * cmv; acc.w += xv.w * cmv;
        *reinterpret_cast<float4*>(&out[base + p0]) = acc;
    }
    if (MODE == 3) {
        float4 ov = *reinterpret_cast<float4*>(&out[base + p0]);
        acc.x += ov.x; acc.y += ov.y; acc.z += ov.z; acc.w += ov.w;
        *reinterpret_cast<float4*>(&out[base + p0]) = acc;
    }
}

// ---------------------------------------------------------------------------
extern "C" void kernel_launch(void* const* d_in, const int* in_sizes, int n_in,
                              void* d_out, int out_size) {
    (void)in_sizes; (void)n_in; (void)out_size;
    const float* x    = (const float*)d_in[0];
    const float* a1   = (const float*)d_in[1];
    const float* a2   = (const float*)d_in[2];
    const float* W1_0 = (const float*)d_in[3];
    const float* W2_0 = (const float*)d_in[4];
    const float* W1_1 = (const float*)d_in[5];
    const float* W2_1 = (const float*)d_in[6];
    const float* W1_4 = (const float*)d_in[7];
    const float* W2_4 = (const float*)d_in[8];
    const float* W1_5 = (const float*)d_in[9];
    const float* W2_5 = (const float*)d_in[10];
    float* out = (float*)d_out;

    cudaFuncSetAttribute(conv_kernel<1, 0>, cudaFuncAttributeMaxDynamicSharedMemorySize, SMEM_BYTES);
    cudaFuncSetAttribute(conv_kernel<1, 1>, cudaFuncAttributeMaxDynamicSharedMemorySize, SMEM_BYTES);
    cudaFuncSetAttribute(conv_kernel<1, 2>, cudaFuncAttributeMaxDynamicSharedMemorySize, SMEM_BYTES);
    cudaFuncSetAttribute(conv_kernel<2, 0>, cudaFuncAttributeMaxDynamicSharedMemorySize, SMEM_BYTES);

    prep_kernel<<<1, 64>>>(a1, a2);

    // n1 = nor_conv(x, W1_0, W2_0)
    conv_kernel<1, 0><<<256, 256, SMEM_BYTES>>>(x, W1_0);
    fin1_kernel<<<1, 64>>>();
    conv_kernel<2, 0><<<256, 256, SMEM_BYTES>>>(nullptr, W2_0);
    fin2_kernel<<<1, 64>>>(a2);
    combine_kernel<0><<<4096, 256>>>(nullptr, nullptr);

    // n2 = nor_conv(x, W1_1, W2_1) + avgpool3(n1)*cm
    conv_kernel<1, 0><<<256, 256, SMEM_BYTES>>>(x, W1_1);
    fin1_kernel<<<1, 64>>>();
    conv_kernel<2, 0><<<256, 256, SMEM_BYTES>>>(nullptr, W2_1);
    fin2_kernel<<<1, 64>>>(a2);
    combine_kernel<1><<<4096, 256>>>(nullptr, nullptr);

    // out = x*cm + nor_conv(n1, W1_4, W2_4)
    conv_kernel<1, 1><<<256, 256, SMEM_BYTES>>>(nullptr, W1_4);
    fin1_kernel<<<1, 64>>>();
    conv_kernel<2, 0><<<256, 256, SMEM_BYTES>>>(nullptr, W2_4);
    fin2_kernel<<<1, 64>>>(a2);
    combine_kernel<2><<<4096, 256>>>(x, out);

    // out += nor_conv(n2, W1_5, W2_5)
    conv_kernel<1, 2><<<256, 256, SMEM_BYTES>>>(nullptr, W1_5);
    fin1_kernel<<<1, 64>>>();
    conv_kernel<2, 0><<<256, 256, SMEM_BYTES>>>(nullptr, W2_5);
    fin2_kernel<<<1, 64>>>(a2);
    combine_kernel<3><<<4096, 256>>>(nullptr, out);
}

// round 8
// speedup vs baseline: 1.0727x; 1.0727x over previous
#include <cuda_runtime.h>
#include <stdint.h>

typedef unsigned long long u64;
#define EPSV 1e-5f
#define CI_STRIDE   1360     // 34 rows * 40 cols
#define BUF_STRIDE  10880    // 8 ci * CI_STRIDE
#define SMEM_BYTES  (24576 * 4)   // sIn 21760 | sW 2304 | sStat 512

__device__ float  g_C1[2][(size_t)64 * 64 * 1024];
__device__ float  g_P [2][(size_t)8 * 64 * 64 * 1024];
__device__ float  g_N1 [(size_t)64 * 64 * 1024];
__device__ float  g_Xr [(size_t)64 * 64 * 1024];
__device__ float  g_N1r[(size_t)64 * 64 * 1024];
__device__ float  g_N2r[(size_t)64 * 64 * 1024];
__device__ float2 g_part1[2][64 * 64];
__device__ float2 g_part2[2][8 * 64 * 64];
__device__ float  g_scale1[2][64], g_shift1[2][64];
__device__ float  g_scaleP[2][8 * 64];
__device__ float  g_biasP[2][64];
__device__ float  g_m1v[64], g_cmv[64];
__device__ float  g_Wt[(size_t)8 * 32 * 1152];   // [set][ocb*8+cc][r=ci*9+tap][16 oc]

__device__ __forceinline__ u64 fma2(u64 a, u64 b, u64 c) {
    u64 d; asm("fma.rn.f32x2 %0, %1, %2, %3;" : "=l"(d) : "l"(a), "l"(b), "l"(c)); return d;
}
__device__ __forceinline__ u64 pack2(float x, float y) {
    u64 d; asm("mov.b64 %0, {%1, %2};" : "=l"(d) : "f"(x), "f"(y)); return d;
}
__device__ __forceinline__ float2 unpack2(u64 v) {
    float2 r; asm("mov.b64 {%0, %1}, %2;" : "=f"(r.x), "=f"(r.y) : "l"(v)); return r;
}
__device__ __forceinline__ void cpa16(uint32_t s, const float* g) {
    asm volatile("cp.async.cg.shared.global [%0], [%1], 16;" :: "r"(s), "l"(g));
}
__device__ __forceinline__ void cpa_commit() { asm volatile("cp.async.commit_group;"); }
template <int N> __device__ __forceinline__ void cpa_wait() {
    asm volatile("cp.async.wait_group %0;" :: "n"(N));
}

__device__ __forceinline__ void warp_reduce32(float* v, int lane) {
#pragma unroll
    for (int d = 16; d >= 1; d >>= 1)
#pragma unroll
        for (int i = 0; i < d; ++i) {
            float mine = (lane & d) ? v[i + d] : v[i];
            float give = (lane & d) ? v[i]     : v[i + d];
            v[i] = mine + __shfl_xor_sync(0xffffffffu, give, d);
        }
}

// ------------------------------ prep kernels -------------------------------
__global__ void prep_small(const float* __restrict__ a1, const float* __restrict__ a2) {
    int c = threadIdx.x, g = c >> 3;
    float s1 = 0.f, s2 = 0.f;
    for (int i = g; i < 8; ++i) { s1 += a1[i]; s2 += a2[i]; }
    g_m1v[c] = s1; g_cmv[c] = s1 * s2;
}

__global__ void relux_kernel(const float* __restrict__ x) {   // <<<4096,256>>> float4
    size_t i = (size_t)blockIdx.x * 256 + threadIdx.x;
    float4 v = reinterpret_cast<const float4*>(x)[i];
    v.x = fmaxf(v.x, 0.f); v.y = fmaxf(v.y, 0.f);
    v.z = fmaxf(v.z, 0.f); v.w = fmaxf(v.w, 0.f);
    reinterpret_cast<float4*>(g_Xr)[i] = v;
}

// sets: 0:W1_0 1:W1_1 2:W2_0 3:W2_1 4:W1_4 5:W1_5 6:W2_4 7:W2_5
__global__ void wtrans_kernel(const float* p0, const float* p1, const float* p2, const float* p3,
                              const float* p4, const float* p5, const float* p6, const float* p7) {
    int setid = blockIdx.x >> 5;            // <<<256,256>>>
    int blk = blockIdx.x & 31;
    int ocb = blk >> 3, cc = blk & 7;
    const float* w = setid == 0 ? p0 : setid == 1 ? p1 : setid == 2 ? p2 : setid == 3 ? p3
                   : setid == 4 ? p4 : setid == 5 ? p5 : setid == 6 ? p6 : p7;
    float* dst = g_Wt + ((size_t)setid * 32 + blk) * 1152;
    for (int i = threadIdx.x; i < 1152; i += 256) {
        int o = i & 15, r = i >> 4;
        int ci = r / 9, tap = r - ci * 9;
        dst[i] = w[((size_t)(ocb * 16 + o) * 64 + cc * 8 + ci) * 9 + tap];
    }
}

// g_C1[e] <- g_C1[e]*scale1[e][c] + shift1[e][c]   (in place)  <<<8192,256>>> float4
__global__ void c1_affine_kernel() {
    size_t i = (size_t)blockIdx.x * 256 + threadIdx.x;   // float4 index, 2^21 total
    int e = (int)(i >> 20);
    int c = (int)(i >> 8) & 63;
    float sc = g_scale1[e][c], sh = g_shift1[e][c];
    float4* p = reinterpret_cast<float4*>(&g_C1[0][0]) + i;
    float4 v = *p;
    v.x = fmaf(v.x, sc, sh); v.y = fmaf(v.y, sc, sh);
    v.z = fmaf(v.z, sc, sh); v.w = fmaf(v.w, sc, sh);
    *p = v;
}

// --------------------------- conv (merged pair) ----------------------------
__device__ __forceinline__ void issue_group(uint32_t sInU, uint32_t sWU,
    const float* __restrict__ src, const float* __restrict__ wgrp, int b, int cbase, int t)
{
    int row = t >> 3, chunk = t & 7;
    const float* g = src + (((size_t)b * 64 + cbase) << 10) + (row << 5) + (chunk << 2);
    uint32_t d = sInU + (((row + 1) * 40 + 4 + (chunk << 2)) << 2);
#pragma unroll
    for (int ci = 0; ci < 8; ++ci)
        cpa16(d + ci * (CI_STRIDE * 4), g + ((size_t)ci << 10));
    cpa16(sWU + t * 16, wgrp + t * 4);
    if (t < 32) cpa16(sWU + (256 + t) * 16, wgrp + (256 + t) * 4);
}

// grid 512: e = bx>>8, b = (bx>>2)&63, ocb = bx&3
template <int STAGE, int PAIR>
__global__ __launch_bounds__(256, 2)
void conv_pair_kernel() {
    extern __shared__ float smem[];
    float* sIn   = smem;
    float* sW    = smem + 21760;
    float* sStat = smem + 24064;
    uint32_t sInU = (uint32_t)__cvta_generic_to_shared(sIn);
    uint32_t sWU  = (uint32_t)__cvta_generic_to_shared(sW);

    const int e   = blockIdx.x >> 8;
    const int b   = (blockIdx.x >> 2) & 63;
    const int ocb = blockIdx.x & 3;
    const int oc0 = ocb << 4;
    const int t   = threadIdx.x;
    const int tx  = t & 31, ty = t >> 5;
    const int lane = tx, wid = ty;

    const float* src = (STAGE == 2) ? g_C1[e]
                     : (PAIR == 0)  ? g_Xr
                     : (e ? g_N2r : g_N1r);
    const int setid = PAIR * 4 + (STAGE - 1) * 2 + e;
    const float* wt = g_Wt + ((size_t)setid * 32 + ocb * 8) * 1152;
    float* gPe = g_P[e];

    // halo zero, both buffers: rows 0/33 full + cols 3/36 of rows 1..32
    for (int i = t; i < 2304; i += 256) {
        int bc = i / 144;
        int r  = i - bc * 144;
        float* base = sIn + bc * CI_STRIDE;
        if (r < 40)      base[r] = 0.f;
        else if (r < 80) base[33 * 40 + (r - 40)] = 0.f;
        else { int rr = r - 80; base[((rr >> 1) + 1) * 40 + ((rr & 1) ? 36 : 3)] = 0.f; }
    }

    u64 acc2[4][8];
#pragma unroll
    for (int p = 0; p < 4; ++p)
#pragma unroll
        for (int o2 = 0; o2 < 8; ++o2) acc2[p][o2] = 0ull;

    issue_group(sInU, sWU, src, wt, b, 0, t);
    cpa_commit();

#pragma unroll 1
    for (int cc = 0; cc < 8; ++cc) {
        const int cur = cc & 1;
        if (cc < 7) {
            issue_group(sInU + (cur ^ 1) * (BUF_STRIDE * 4), sWU + (cur ^ 1) * (1152 * 4),
                        src, wt + (cc + 1) * 1152, b, (cc + 1) << 3, t);
            cpa_commit();
            cpa_wait<1>();
        } else {
            cpa_wait<0>();
        }
        __syncthreads();

        const float* buf = sIn + cur * BUF_STRIDE;
        const float* wb  = sW + cur * 1152;
#pragma unroll 1
        for (int ci = 0; ci < 8; ++ci) {
            const float* bci = buf + ci * CI_STRIDE;
            const float* wci = wb + (ci * 9 << 4);
#pragma unroll
            for (int ky = 0; ky < 3; ++ky) {
#pragma unroll
                for (int kx = 0; kx < 3; ++kx) {
                    const float* wrow = wci + ((ky * 3 + kx) << 4);
                    u64 wp[8];
#pragma unroll
                    for (int o2 = 0; o2 < 8; ++o2)
                        wp[o2] = *reinterpret_cast<const u64*>(wrow + (o2 << 1));
#pragma unroll
                    for (int p = 0; p < 4; ++p) {
                        float iv = bci[(ty + (p << 3) + ky) * 40 + tx + kx + 3];
                        u64 iv2 = pack2(iv, iv);
#pragma unroll
                        for (int o2 = 0; o2 < 8; ++o2)
                            acc2[p][o2] = fma2(iv2, wp[o2], acc2[p][o2]);
                    }
                }
            }
        }

        if (STAGE == 2) {      // prefix boundary: emit P_cc + stats
            float v[32];
#pragma unroll
            for (int o = 0; o < 32; ++o) v[o] = 0.f;
#pragma unroll
            for (int p = 0; p < 4; ++p) {
                int pix = ((ty + (p << 3)) << 5) + tx;
#pragma unroll
                for (int o2 = 0; o2 < 8; ++o2) {
                    float2 pv = unpack2(acc2[p][o2]);
                    size_t base = (((size_t)cc * 64 + b) * 64 + oc0 + (o2 << 1)) * 1024 + pix;
                    gPe[base]        = pv.x;
                    gPe[base + 1024] = pv.y;
                    v[2 * o2]          += pv.x;
                    v[16 + 2 * o2]     += pv.x * pv.x;
                    v[2 * o2 + 1]      += pv.y;
                    v[16 + 2 * o2 + 1] += pv.y * pv.y;
                }
            }
            warp_reduce32(v, lane);
            sStat[cur * 256 + (wid << 5) + lane] = v[0];
        }
        __syncthreads();
        if (STAGE == 2 && t < 32) {
            float s = 0.f;
#pragma unroll
            for (int ww = 0; ww < 8; ++ww) s += sStat[cur * 256 + (ww << 5) + lane];
            float qv = __shfl_down_sync(0xffffffffu, s, 16);
            if (lane < 16)
                g_part2[e][((size_t)cc * 64 + oc0 + lane) * 64 + b] = make_float2(s, qv);
        }
    }

    if (STAGE == 1) {
        float v[32];
#pragma unroll
        for (int o = 0; o < 32; ++o) v[o] = 0.f;
        float* gC = g_C1[e];
#pragma unroll
        for (int p = 0; p < 4; ++p) {
            int pix = ((ty + (p << 3)) << 5) + tx;
#pragma unroll
            for (int o2 = 0; o2 < 8; ++o2) {
                float2 pv = unpack2(acc2[p][o2]);
                size_t base = (((size_t)b * 64 + oc0 + (o2 << 1)) << 10) + pix;
                gC[base]        = pv.x;
                gC[base + 1024] = pv.y;
                v[2 * o2]          += pv.x;
                v[16 + 2 * o2]     += pv.x * pv.x;
                v[2 * o2 + 1]      += pv.y;
                v[16 + 2 * o2 + 1] += pv.y * pv.y;
            }
        }
        warp_reduce32(v, lane);
        sStat[(wid << 5) + lane] = v[0];
        __syncthreads();
        if (t < 32) {
            float s = 0.f;
#pragma unroll
            for (int ww = 0; ww < 8; ++ww) s += sStat[(ww << 5) + lane];
            float qv = __shfl_down_sync(0xffffffffu, s, 16);
            if (lane < 16)
                g_part1[e][(oc0 + lane) * 64 + b] = make_float2(s, qv);
        }
    }
}

// ------------------------------- finalizers --------------------------------
__global__ void fin1_pair() {   // <<<1,128>>>
    int e = threadIdx.x >> 6, c = threadIdx.x & 63;
    float s = 0.f, q = 0.f;
    for (int b = 0; b < 64; ++b) { float2 v = g_part1[e][c * 64 + b]; s += v.x; q += v.y; }
    const float invN = 1.f / 65536.f;
    float mu = s * invN;
    float var = q * invN - mu * mu;
    float sc = rsqrtf(var + EPSV) * g_m1v[c];
    g_scale1[e][c] = sc;
    g_shift1[e][c] = -mu * sc;
}

__global__ void fin2_pair(const float* __restrict__ a2) {   // <<<1,128>>>
    int e = threadIdx.x >> 6, c = threadIdx.x & 63;
    const float invN = 1.f / 65536.f;
    float bias = 0.f;
    for (int k = 0; k < 8; ++k) {
        float s = 0.f, q = 0.f;
        for (int b = 0; b < 64; ++b) { float2 v = g_part2[e][(k * 64 + c) * 64 + b]; s += v.x; q += v.y; }
        float mu = s * invN;
        float var = q * invN - mu * mu;
        float wk = a2[k] * rsqrtf(var + EPSV);
        g_scaleP[e][k * 64 + c] = wk;
        bias -= wk * mu;
    }
    g_biasP[e][c] = bias;
}

// -------------------------------- combines ---------------------------------
__device__ __forceinline__ float4 comb_acc(int E, int b, int c, int p0) {
    float bias = g_biasP[E][c];
    float4 acc = make_float4(bias, bias, bias, bias);
#pragma unroll
    for (int k = 0; k < 8; ++k) {
        float sp = g_scaleP[E][k * 64 + c];
        float4 v = *reinterpret_cast<const float4*>(
            &g_P[E][(((size_t)k * 64 + b) * 64 + c) * 1024 + p0]);
        acc.x = fmaf(sp, v.x, acc.x); acc.y = fmaf(sp, v.y, acc.y);
        acc.z = fmaf(sp, v.z, acc.z); acc.w = fmaf(sp, v.w, acc.w);
    }
    return acc;
}

__global__ __launch_bounds__(256)
void combine0_kernel() {   // n1 -> g_N1, relu(n1) -> g_N1r   <<<4096,256>>>
    int bc = blockIdx.x, b = bc >> 6, c = bc & 63;
    int p0 = threadIdx.x << 2;
    size_t base = ((size_t)b * 64 + c) << 10;
    float4 acc = comb_acc(0, b, c, p0);
    *reinterpret_cast<float4*>(&g_N1[base + p0]) = acc;
    acc.x = fmaxf(acc.x, 0.f); acc.y = fmaxf(acc.y, 0.f);
    acc.z = fmaxf(acc.z, 0.f); acc.w = fmaxf(acc.w, 0.f);
    *reinterpret_cast<float4*>(&g_N1r[base + p0]) = acc;
}

__global__ __launch_bounds__(256)
void combine1_kernel() {   // relu(n2) -> g_N2r, n2 = comb1 + avgpool3(n1)*cm
    int bc = blockIdx.x, b = bc >> 6, c = bc & 63;
    int p0 = threadIdx.x << 2;
    size_t base = ((size_t)b * 64 + c) << 10;
    float4 acc = comb_acc(1, b, c, p0);
    float cmv = g_cmv[c];
    int y = p0 >> 5, x = p0 & 31;
    int y0 = max(y - 1, 0), y1 = min(y + 1, 31);
    float rs[6];
#pragma unroll
    for (int j = 0; j < 6; ++j) {
        int xx = x - 1 + j;
        float v = 0.f;
        if ((unsigned)xx < 32u)
            for (int yy = y0; yy <= y1; ++yy) v += g_N1[base + (yy << 5) + xx];
        rs[j] = v;
    }
    float nr = (float)(y1 - y0 + 1);
    float pool[4];
#pragma unroll
    for (int i = 0; i < 4; ++i) {
        int xi = x + i;
        int c0 = max(xi - 1, 0), c1 = min(xi + 1, 31);
        pool[i] = (rs[i] + rs[i + 1] + rs[i + 2]) / (nr * (float)(c1 - c0 + 1));
    }
    acc.x = fmaxf(fmaf(pool[0], cmv, acc.x), 0.f);
    acc.y = fmaxf(fmaf(pool[1], cmv, acc.y), 0.f);
    acc.z = fmaxf(fmaf(pool[2], cmv, acc.z), 0.f);
    acc.w = fmaxf(fmaf(pool[3], cmv, acc.w), 0.f);
    *reinterpret_cast<float4*>(&g_N2r[base + p0]) = acc;
}

__global__ __launch_bounds__(256)
void combineF_kernel(const float* __restrict__ xin, float* __restrict__ out) {
    int bc = blockIdx.x, b = bc >> 6, c = bc & 63;
    int p0 = threadIdx.x << 2;
    size_t base = ((size_t)b * 64 + c) << 10;
    float4 a0 = comb_acc(0, b, c, p0);
    float4 a1 = comb_acc(1, b, c, p0);
    float cmv = g_cmv[c];
    float4 xv = *reinterpret_cast<const float4*>(&xin[base + p0]);
    a0.x += a1.x + xv.x * cmv; a0.y += a1.y + xv.y * cmv;
    a0.z += a1.z + xv.z * cmv; a0.w += a1.w + xv.w * cmv;
    *reinterpret_cast<float4*>(&out[base + p0]) = a0;
}

// ---------------------------------------------------------------------------
extern "C" void kernel_launch(void* const* d_in, const int* in_sizes, int n_in,
                              void* d_out, int out_size) {
    (void)in_sizes; (void)n_in; (void)out_size;
    const float* x    = (const float*)d_in[0];
    const float* a1   = (const float*)d_in[1];
    const float* a2   = (const float*)d_in[2];
    const float* W1_0 = (const float*)d_in[3];
    const float* W2_0 = (const float*)d_in[4];
    const float* W1_1 = (const float*)d_in[5];
    const float* W2_1 = (const float*)d_in[6];
    const float* W1_4 = (const float*)d_in[7];
    const float* W2_4 = (const float*)d_in[8];
    const float* W1_5 = (const float*)d_in[9];
    const float* W2_5 = (const float*)d_in[10];
    float* out = (float*)d_out;

    cudaFuncSetAttribute(conv_pair_kernel<1, 0>, cudaFuncAttributeMaxDynamicSharedMemorySize, SMEM_BYTES);
    cudaFuncSetAttribute(conv_pair_kernel<2, 0>, cudaFuncAttributeMaxDynamicSharedMemorySize, SMEM_BYTES);
    cudaFuncSetAttribute(conv_pair_kernel<1, 1>, cudaFuncAttributeMaxDynamicSharedMemorySize, SMEM_BYTES);
    cudaFuncSetAttribute(conv_pair_kernel<2, 1>, cudaFuncAttributeMaxDynamicSharedMemorySize, SMEM_BYTES);

    prep_small<<<1, 64>>>(a1, a2);
    wtrans_kernel<<<256, 256>>>(W1_0, W1_1, W2_0, W2_1, W1_4, W1_5, W2_4, W2_5);
    relux_kernel<<<4096, 256>>>(x);

    // pair 0: edges 0 (->n1) and 1 (->n2)
    conv_pair_kernel<1, 0><<<512, 256, SMEM_BYTES>>>();
    fin1_pair<<<1, 128>>>();
    c1_affine_kernel<<<8192, 256>>>();
    conv_pair_kernel<2, 0><<<512, 256, SMEM_BYTES>>>();
    fin2_pair<<<1, 128>>>(a2);
    combine0_kernel<<<4096, 256>>>();
    combine1_kernel<<<4096, 256>>>();

    // pair 1: edges 4 (conv(n1)) and 5 (conv(n2))
    conv_pair_kernel<1, 1><<<512, 256, SMEM_BYTES>>>();
    fin1_pair<<<1, 128>>>();
    c1_affine_kernel<<<8192, 256>>>();
    conv_pair_kernel<2, 1><<<512, 256, SMEM_BYTES>>>();
    fin2_pair<<<1, 128>>>(a2);
    combineF_kernel<<<4096, 256>>>(x, out);
}